// round 14
// baseline (speedup 1.0000x reference)
#include <cuda_runtime.h>

// Problem constants (shapes fixed by the dataset)
#define NMAX   100000
#define EMAX   3200000
#define F_INC  256
#define HIDC   16
#define CLSC   16
#define KST    2
#define JW     (KST*HIDC)   // 32 = fused K*HID width for layer-1 tensors

// ---------------- device scratch (no allocations allowed) ----------------
__device__ int   g_is64;
__device__ __align__(16) int   g_degi  [NMAX];
__device__ __align__(16) int   g_rowinc[NMAX];      // inclusive scan within block
__device__ __align__(16) int   g_rowptr[NMAX + 1];
__device__ __align__(16) int   g_cur   [NMAX];
__device__ __align__(16) int   g_bsum  [1024];
__device__ __align__(16) int   g_csr   [EMAX];      // src per CSR slot (grouped by dst)
__device__ __align__(16) float g_dinv  [NMAX];
__device__ __align__(16) float g_h1    [NMAX * JW]; // dinv[n] * (x @ init_w1), both stacks
__device__ __align__(16) float g_r1    [NMAX * JW]; // x @ root_w1
__device__ __align__(16) float g_agg1  [NMAX * JW];
__device__ __align__(16) float g_hf    [NMAX * HIDC]; // relu-mean feature h
__device__ __align__(16) float g_hfs   [NMAX * HIDC]; // dinv[n] * h  (gather operand)
__device__ __align__(16) float g_aggh  [NMAX * HIDC]; // S @ h

// ---------------- f32x2 packed-FMA helpers (Blackwell) ----------------
__device__ __forceinline__ unsigned long long pk2(float x) {
    unsigned long long r;
    asm("mov.b64 %0, {%1,%2};" : "=l"(r) : "f"(x), "f"(x));
    return r;
}
__device__ __forceinline__ void ffma2(unsigned long long& d,
                                      unsigned long long a,
                                      unsigned long long b) {
    asm("fma.rn.f32x2 %0, %1, %2, %0;" : "+l"(d) : "l"(a), "l"(b));
}

// ---------------- dtype detector: int64 vs int32 edge_index ----------------
// Node ids < 100000. If little-endian int64, every odd 32-bit word is 0.
// Parallel: 256 threads each test 4 odd words; __syncthreads_count reduces.
__global__ void detect_kernel(const unsigned int* __restrict__ ei) {
    int t = threadIdx.x;
    int nz = 0;
    #pragma unroll
    for (int i = 0; i < 4; i++)
        nz += (ei[(t * 4 + i) * 2 + 1] != 0u);
    int total = __syncthreads_count(nz != 0);
    if (t == 0) g_is64 = (total == 0) ? 1 : 0;
}

__device__ __forceinline__ int load_idx(const void* ei, long long i) {
    if (g_is64) return (int)((const long long*)ei)[i];
    return ((const int*)ei)[i];
}

// ---------------- zero degree counters ----------------
__global__ void zeroi_kernel(int N) {
    int i = blockIdx.x * blockDim.x + threadIdx.x;
    if (i < N) g_degi[i] = 0;
}

// ---------------- degree (from dst / col index, matching gcn_norm) --------
__global__ void deg_kernel(const void* __restrict__ ei, int E) {
    int e = blockIdx.x * blockDim.x + threadIdx.x;
    if (e >= E) return;
    int d = load_idx(ei, (long long)E + e);
    atomicAdd(&g_degi[d], 1);
}

// ---------------- 3-step exclusive scan of degrees -> rowptr --------------
__global__ __launch_bounds__(256) void scan1_kernel(int N) {
    __shared__ int wsum[8];
    int t = threadIdx.x;
    int n = blockIdx.x * 256 + t;
    int v = (n < N) ? g_degi[n] : 0;
    int x = v;
    #pragma unroll
    for (int o = 1; o < 32; o <<= 1) {
        int y = __shfl_up_sync(0xffffffffu, x, o);
        if ((t & 31) >= o) x += y;
    }
    if ((t & 31) == 31) wsum[t >> 5] = x;
    __syncthreads();
    if (t == 0) {
        int run = 0;
        #pragma unroll
        for (int i = 0; i < 8; i++) { int tmp = wsum[i]; wsum[i] = run; run += tmp; }
        g_bsum[blockIdx.x] = run;
    }
    __syncthreads();
    if (n < N) g_rowinc[n] = x + wsum[t >> 5];   // inclusive within block
}

__global__ __launch_bounds__(512) void scan2_kernel(int nb) {
    __shared__ int ws[16];
    int t = threadIdx.x;
    int v = (t < nb) ? g_bsum[t] : 0;
    int x = v;
    #pragma unroll
    for (int o = 1; o < 32; o <<= 1) {
        int y = __shfl_up_sync(0xffffffffu, x, o);
        if ((t & 31) >= o) x += y;
    }
    if ((t & 31) == 31) ws[t >> 5] = x;
    __syncthreads();
    if (t == 0) {
        int run = 0;
        #pragma unroll
        for (int i = 0; i < 16; i++) { int tmp = ws[i]; ws[i] = run; run += tmp; }
    }
    __syncthreads();
    if (t < nb) g_bsum[t] = x + ws[t >> 5] - v;  // exclusive block offsets
}

__global__ __launch_bounds__(256) void scan3_kernel(int N) {
    int n = blockIdx.x * 256 + threadIdx.x;
    if (n >= N) return;
    int d     = g_degi[n];
    int start = g_bsum[blockIdx.x] + g_rowinc[n] - d;
    g_rowptr[n] = start;
    g_cur[n]    = start;
    g_dinv[n]   = (d > 0) ? rsqrtf((float)d) : 0.f;
    if (n == N - 1) g_rowptr[N] = start + d;     // == E
}

// ---------------- CSR fill: csr[pos] = src, grouped by dst ----------------
__global__ void fill_kernel(const void* __restrict__ ei, int E) {
    int e = blockIdx.x * blockDim.x + threadIdx.x;
    if (e >= E) return;
    int s = load_idx(ei, e);
    int d = load_idx(ei, (long long)E + e);
    int pos = atomicAdd(&g_cur[d], 1);
    g_csr[pos] = s;
}

// ---------------- GEMM1: h1 = dinv*(x @ init_w1), r1 = x @ root_w1 --------
// Block: 256 threads, 64 nodes. Thread (nid=t/4, jq=t%4) computes 16 outputs
// as 8 packed f32x2 accumulators (numerics proven identical in R10).
// ws reads xor-rotated by jq: banks {0-3,20-23,8-11,28-31} -> conflict-free.
__global__ __launch_bounds__(256) void gemm1_kernel(
    const float* __restrict__ x,
    const float* __restrict__ iw,   // [K, F_IN, HID]
    const float* __restrict__ rw,   // [K, F_IN, HID]
    int N)
{
    __shared__ __align__(16) float xs[64][65];    // padded: conflict-free
    __shared__ __align__(16) float ws[64][64];    // ws[fl][j]: j<32 init, j>=32 root

    int t   = threadIdx.x;
    int n0  = blockIdx.x * 64;
    int nid = t >> 2;
    int jq  = t & 3;
    int n   = n0 + nid;

    unsigned long long acc[8];
    #pragma unroll
    for (int o = 0; o < 8; o++) acc[o] = 0ull;   // bit pattern {0.f, 0.f}

    for (int f0 = 0; f0 < F_INC; f0 += 64) {
        #pragma unroll
        for (int i = 0; i < 4; i++) {
            int idx = t + i * 256;
            int nn  = idx >> 4;
            int fq  = idx & 15;
            float4 v = make_float4(0.f, 0.f, 0.f, 0.f);
            if (n0 + nn < N)
                v = *(const float4*)&x[(long long)(n0 + nn) * F_INC + f0 + fq * 4];
            xs[nn][fq * 4 + 0] = v.x;
            xs[nn][fq * 4 + 1] = v.y;
            xs[nn][fq * 4 + 2] = v.z;
            xs[nn][fq * 4 + 3] = v.w;
        }
        #pragma unroll
        for (int i = 0; i < 16; i++) {
            int idx = t + i * 256;
            int fl  = idx >> 6;
            int j   = idx & 63;
            float v;
            if (j < 32)
                v = iw[(j >> 4) * (F_INC * HIDC) + (f0 + fl) * HIDC + (j & 15)];
            else {
                int jj = j - 32;
                v = rw[(jj >> 4) * (F_INC * HIDC) + (f0 + fl) * HIDC + (jj & 15)];
            }
            ws[fl][j] = v;
        }
        __syncthreads();

        #pragma unroll 8
        for (int fl = 0; fl < 64; fl++) {
            unsigned long long xd = pk2(xs[nid][fl]);
            #pragma unroll
            for (int m = 0; m < 4; m++) {
                int i = (m + jq) & 3;       // xor-rotated: conflict-free LDS.128
                ulonglong2 wv = *(const ulonglong2*)&ws[fl][jq * 16 + i * 4];
                ffma2(acc[2 * i + 0], xd, wv.x);
                ffma2(acc[2 * i + 1], xd, wv.y);
            }
        }
        __syncthreads();
    }

    if (n < N) {
        float r[16];
        #pragma unroll
        for (int i = 0; i < 8; i++) {
            asm("mov.b64 {%0,%1}, %2;" : "=f"(r[2 * i]), "=f"(r[2 * i + 1])
                                       : "l"(acc[i]));
        }
        bool hpath = (jq < 2);
        float scale = hpath ? g_dinv[n] : 1.0f;   // fold dinv[src] into h1 rows
        #pragma unroll
        for (int o = 0; o < 16; o++) r[o] *= scale;
        float* base = hpath ? &g_h1[n * JW + jq * 16]
                            : &g_r1[n * JW + (jq - 2) * 16];
        float4* d4 = (float4*)base;
        d4[0] = make_float4(r[0],  r[1],  r[2],  r[3]);
        d4[1] = make_float4(r[4],  r[5],  r[6],  r[7]);
        d4[2] = make_float4(r[8],  r[9],  r[10], r[11]);
        d4[3] = make_float4(r[12], r[13], r[14], r[15]);
    }
}

// ---------------- pull aggregation, width 32: warp per node ----------------
// agg1[n][c] = dinv[n] * sum_{s in N(n)} h1[s][c]   (h1 pre-scaled by dinv[s])
__global__ __launch_bounds__(256) void gather32_kernel(int N) {
    int warp = (blockIdx.x * blockDim.x + threadIdx.x) >> 5;
    int lane = threadIdx.x & 31;
    if (warp >= N) return;
    int beg = g_rowptr[warp], end = g_rowptr[warp + 1];
    float acc = 0.f;
    for (int i = beg; i < end; i += 32) {
        int idx = (i + lane < end) ? g_csr[i + lane] : 0;
        int m = min(32, end - i);
        for (int j = 0; j < m; j++) {
            int s = __shfl_sync(0xffffffffu, idx, j);
            acc += g_h1[s * JW + lane];          // 128B coalesced row read
        }
    }
    g_agg1[warp * JW + lane] = acc * g_dinv[warp];
}

// ---------------- pull aggregation, width 16: warp per node, 2 edges/iter --
__global__ __launch_bounds__(256) void gather16_kernel(int N) {
    int warp = (blockIdx.x * blockDim.x + threadIdx.x) >> 5;
    int lane = threadIdx.x & 31;
    if (warp >= N) return;
    int q   = lane & 15;
    int sub = lane >> 4;
    int beg = g_rowptr[warp], end = g_rowptr[warp + 1];
    float acc = 0.f;
    for (int i = beg; i < end; i += 32) {
        int idx = (i + lane < end) ? g_csr[i + lane] : 0;
        int m = min(32, end - i);
        for (int j = 0; j < m; j += 2) {
            int jj = j + sub;
            int s = __shfl_sync(0xffffffffu, idx, jj);
            if (jj < m) acc += g_hfs[s * HIDC + q];   // 2x64B per iter
        }
    }
    acc += __shfl_xor_sync(0xffffffffu, acc, 16);
    if (sub == 0) g_aggh[warp * HIDC + q] = acc * g_dinv[warp];
}

// ---------------- combine conv1: h = mean_k relu(agg + root + bias) --------
__global__ __launch_bounds__(256) void combine_kernel(
    const float* __restrict__ b1,    // [K, HID] = 32
    float* __restrict__ feat_out,
    int N, int write_feat)
{
    __shared__ float b1s[32];
    int t = threadIdx.x;
    if (t < 32) b1s[t] = b1[t];
    __syncthreads();

    int n = blockIdx.x * blockDim.x + t;
    if (n >= N) return;

    float pre[32];
    const float4* a4 = (const float4*)&g_agg1[n * JW];
    const float4* r4 = (const float4*)&g_r1 [n * JW];
    #pragma unroll
    for (int q = 0; q < 8; q++) {
        float4 av = a4[q], rv = r4[q];
        pre[q * 4 + 0] = av.x + rv.x + b1s[q * 4 + 0];
        pre[q * 4 + 1] = av.y + rv.y + b1s[q * 4 + 1];
        pre[q * 4 + 2] = av.z + rv.z + b1s[q * 4 + 2];
        pre[q * 4 + 3] = av.w + rv.w + b1s[q * 4 + 3];
    }
    float h[16];
    #pragma unroll
    for (int o = 0; o < 16; o++) {
        float a0 = fmaxf(pre[o],      0.f);
        float a1 = fmaxf(pre[16 + o], 0.f);
        h[o] = 0.5f * (a0 + a1);   // mean over K; outer relu is a no-op (>=0)
    }
    float dn = g_dinv[n];
    float4 v0 = make_float4(h[0],  h[1],  h[2],  h[3]);
    float4 v1 = make_float4(h[4],  h[5],  h[6],  h[7]);
    float4 v2 = make_float4(h[8],  h[9],  h[10], h[11]);
    float4 v3 = make_float4(h[12], h[13], h[14], h[15]);
    float4* hf4 = (float4*)&g_hf[n * HIDC];
    hf4[0] = v0; hf4[1] = v1; hf4[2] = v2; hf4[3] = v3;
    float4* hs4 = (float4*)&g_hfs[n * HIDC];
    hs4[0] = make_float4(h[0] * dn,  h[1] * dn,  h[2] * dn,  h[3] * dn);
    hs4[1] = make_float4(h[4] * dn,  h[5] * dn,  h[6] * dn,  h[7] * dn);
    hs4[2] = make_float4(h[8] * dn,  h[9] * dn,  h[10] * dn, h[11] * dn);
    hs4[3] = make_float4(h[12] * dn, h[13] * dn, h[14] * dn, h[15] * dn);
    if (write_feat) {
        float4* f4 = (float4*)&feat_out[(long long)n * CLSC];
        f4[0] = v0; f4[1] = v1; f4[2] = v2; f4[3] = v3;
    }
}

// ---------------- final: logits = (S@h)@Wi + h@Wr + b, then log_softmax ----
__global__ __launch_bounds__(256) void final_kernel(
    const float* __restrict__ iw2,   // [K, HID, C]
    const float* __restrict__ rw2,   // [K, HID, C]
    const float* __restrict__ b2,    // [K, C]
    float* __restrict__ out, int N)
{
    __shared__ float wi[16][16], wr[16][16], bs[16];
    int t = threadIdx.x;
    {
        int o = t >> 4, c = t & 15;
        wi[o][c] = 0.5f * (iw2[o * 16 + c] + iw2[256 + o * 16 + c]);
        wr[o][c] = 0.5f * (rw2[o * 16 + c] + rw2[256 + o * 16 + c]);
    }
    if (t < 16) bs[t] = 0.5f * (b2[t] + b2[16 + t]);
    __syncthreads();

    int n = blockIdx.x * blockDim.x + t;
    if (n >= N) return;

    float ah[16], hh[16];
    const float4* a4 = (const float4*)&g_aggh[n * HIDC];
    const float4* h4 = (const float4*)&g_hf [n * HIDC];
    #pragma unroll
    for (int q = 0; q < 4; q++) {
        float4 av = a4[q], hv = h4[q];
        ah[q * 4 + 0] = av.x; ah[q * 4 + 1] = av.y;
        ah[q * 4 + 2] = av.z; ah[q * 4 + 3] = av.w;
        hh[q * 4 + 0] = hv.x; hh[q * 4 + 1] = hv.y;
        hh[q * 4 + 2] = hv.z; hh[q * 4 + 3] = hv.w;
    }
    float lg[16];
    #pragma unroll
    for (int c = 0; c < 16; c++) lg[c] = bs[c];
    #pragma unroll
    for (int o = 0; o < 16; o++) {
        float a = ah[o], h = hh[o];
        #pragma unroll
        for (int c = 0; c < 16; c++)
            lg[c] = fmaf(a, wi[o][c], fmaf(h, wr[o][c], lg[c]));
    }
    float m = -1e30f;
    #pragma unroll
    for (int c = 0; c < 16; c++) m = fmaxf(m, lg[c]);
    float s = 0.f;
    #pragma unroll
    for (int c = 0; c < 16; c++) s += __expf(lg[c] - m);
    float lse = m + __logf(s);

    float4* o4 = (float4*)&out[(long long)n * CLSC];
    o4[0] = make_float4(lg[0] - lse,  lg[1] - lse,  lg[2] - lse,  lg[3] - lse);
    o4[1] = make_float4(lg[4] - lse,  lg[5] - lse,  lg[6] - lse,  lg[7] - lse);
    o4[2] = make_float4(lg[8] - lse,  lg[9] - lse,  lg[10] - lse, lg[11] - lse);
    o4[3] = make_float4(lg[12] - lse, lg[13] - lse, lg[14] - lse, lg[15] - lse);
}

// ---------------- launch ----------------
extern "C" void kernel_launch(void* const* d_in, const int* in_sizes, int n_in,
                              void* d_out, int out_size) {
    const float* x   = (const float*)d_in[0];
    const void*  ei  = d_in[1];                  // int32 or int64, detected on device
    const float* iw1 = (const float*)d_in[2];
    const float* rw1 = (const float*)d_in[3];
    const float* b1  = (const float*)d_in[4];
    const float* iw2 = (const float*)d_in[5];
    const float* rw2 = (const float*)d_in[6];
    const float* b2  = (const float*)d_in[7];
    float* out = (float*)d_out;

    int N = in_sizes[0] / F_INC;
    int E = in_sizes[1] / 2;
    if (N > NMAX) N = NMAX;
    if (E > EMAX) E = EMAX;

    int write_feat = (out_size >= 2 * N * CLSC) ? 1 : 0;
    float* feat_out = write_feat ? (out + (long long)N * CLSC) : out;

    int nb = (N + 255) / 256;                    // scan blocks (<= 1024)

    detect_kernel<<<1, 256>>>((const unsigned int*)ei);
    zeroi_kernel<<<(N + 1023) / 1024, 1024>>>(N);
    deg_kernel<<<(E + 255) / 256, 256>>>(ei, E);
    scan1_kernel<<<nb, 256>>>(N);
    scan2_kernel<<<1, 512>>>(nb);
    scan3_kernel<<<nb, 256>>>(N);
    fill_kernel<<<(E + 255) / 256, 256>>>(ei, E);
    gemm1_kernel<<<(N + 63) / 64, 256>>>(x, iw1, rw1, N);

    int gblocks = (N * 32 + 255) / 256;          // warp per node
    gather32_kernel<<<gblocks, 256>>>(N);

    combine_kernel<<<nb, 256>>>(b1, feat_out, N, write_feat);

    gather16_kernel<<<gblocks, 256>>>(N);

    final_kernel<<<nb, 256>>>(iw2, rw2, b2, out, N);
}

// round 15
// speedup vs baseline: 10.4607x; 10.4607x over previous
#include <cuda_runtime.h>

// Problem constants (shapes fixed by the dataset)
#define NMAX   100000
#define EMAX   3200000
#define F_INC  256
#define HIDC   16
#define CLSC   16
#define KST    2
#define JW     (KST*HIDC)   // 32 = fused K*HID width for layer-1 tensors

// ---------------- device scratch (no allocations allowed) ----------------
__device__ int   g_is64;
__device__ __align__(16) int   g_degi  [NMAX];
__device__ __align__(16) int   g_rowinc[NMAX];      // inclusive scan within block
__device__ __align__(16) int   g_rowptr[NMAX + 1];
__device__ __align__(16) int   g_cur   [NMAX];
__device__ __align__(16) int   g_bsum  [1024];
__device__ __align__(16) int   g_csr   [EMAX];      // src per CSR slot (grouped by dst)
__device__ __align__(16) float g_dinv  [NMAX];
__device__ __align__(16) float g_h1    [NMAX * JW]; // dinv[n] * (x @ init_w1), both stacks
__device__ __align__(16) float g_r1    [NMAX * JW]; // x @ root_w1
__device__ __align__(16) float g_agg1  [NMAX * JW];
__device__ __align__(16) float g_hf    [NMAX * HIDC]; // relu-mean feature h
__device__ __align__(16) float g_hfs   [NMAX * HIDC]; // dinv[n] * h  (gather operand)
__device__ __align__(16) float g_aggh  [NMAX * HIDC]; // S @ h

// ---------------- dtype detector: int64 vs int32 edge_index ----------------
// Node ids < 100000. If little-endian int64, every odd 32-bit word is 0.
__global__ void detect_kernel(const unsigned int* __restrict__ ei) {
    int t = threadIdx.x;
    int nz = 0;
    #pragma unroll
    for (int i = 0; i < 4; i++)
        nz += (ei[(t * 4 + i) * 2 + 1] != 0u);
    int total = __syncthreads_count(nz != 0);
    if (t == 0) g_is64 = (total == 0) ? 1 : 0;
}

__device__ __forceinline__ int load_idx(const void* ei, long long i) {
    if (g_is64) return (int)((const long long*)ei)[i];
    return ((const int*)ei)[i];
}

// ---------------- zero degree counters ----------------
__global__ void zeroi_kernel(int N) {
    int i = blockIdx.x * blockDim.x + threadIdx.x;
    if (i < N) g_degi[i] = 0;
}

// ---------------- degree (from dst / col index, matching gcn_norm) --------
__global__ void deg_kernel(const void* __restrict__ ei, int E) {
    int e = blockIdx.x * blockDim.x + threadIdx.x;
    if (e >= E) return;
    int d = load_idx(ei, (long long)E + e);
    atomicAdd(&g_degi[d], 1);
}

// ---------------- 3-step exclusive scan of degrees -> rowptr --------------
__global__ __launch_bounds__(256) void scan1_kernel(int N) {
    __shared__ int wsum[8];
    int t = threadIdx.x;
    int n = blockIdx.x * 256 + t;
    int v = (n < N) ? g_degi[n] : 0;
    int x = v;
    #pragma unroll
    for (int o = 1; o < 32; o <<= 1) {
        int y = __shfl_up_sync(0xffffffffu, x, o);
        if ((t & 31) >= o) x += y;
    }
    if ((t & 31) == 31) wsum[t >> 5] = x;
    __syncthreads();
    if (t == 0) {
        int run = 0;
        #pragma unroll
        for (int i = 0; i < 8; i++) { int tmp = wsum[i]; wsum[i] = run; run += tmp; }
        g_bsum[blockIdx.x] = run;
    }
    __syncthreads();
    if (n < N) g_rowinc[n] = x + wsum[t >> 5];   // inclusive within block
}

__global__ __launch_bounds__(512) void scan2_kernel(int nb) {
    __shared__ int ws[16];
    int t = threadIdx.x;
    int v = (t < nb) ? g_bsum[t] : 0;
    int x = v;
    #pragma unroll
    for (int o = 1; o < 32; o <<= 1) {
        int y = __shfl_up_sync(0xffffffffu, x, o);
        if ((t & 31) >= o) x += y;
    }
    if ((t & 31) == 31) ws[t >> 5] = x;
    __syncthreads();
    if (t == 0) {
        int run = 0;
        #pragma unroll
        for (int i = 0; i < 16; i++) { int tmp = ws[i]; ws[i] = run; run += tmp; }
    }
    __syncthreads();
    if (t < nb) g_bsum[t] = x + ws[t >> 5] - v;  // exclusive block offsets
}

__global__ __launch_bounds__(256) void scan3_kernel(int N) {
    int n = blockIdx.x * 256 + threadIdx.x;
    if (n >= N) return;
    int d     = g_degi[n];
    int start = g_bsum[blockIdx.x] + g_rowinc[n] - d;
    g_rowptr[n] = start;
    g_cur[n]    = start;
    g_dinv[n]   = (d > 0) ? rsqrtf((float)d) : 0.f;
    if (n == N - 1) g_rowptr[N] = start + d;     // == E
}

// ---------------- CSR fill: csr[pos] = src, grouped by dst ----------------
__global__ void fill_kernel(const void* __restrict__ ei, int E) {
    int e = blockIdx.x * blockDim.x + threadIdx.x;
    if (e >= E) return;
    int s = load_idx(ei, e);
    int d = load_idx(ei, (long long)E + e);
    int pos = atomicAdd(&g_cur[d], 1);
    g_csr[pos] = s;
}

// ---------------- GEMM1: h1 = dinv*(x @ init_w1), r1 = x @ root_w1 --------
// Block: 256 threads, 64 nodes. Thread (nid = t/4, jq = t%4) computes 16 outputs.
// (R11/R12-proven scalar-FFMA version. f32x2 is BANNED: +5.3ms, see R10/R14.)
__global__ __launch_bounds__(256) void gemm1_kernel(
    const float* __restrict__ x,
    const float* __restrict__ iw,   // [K, F_IN, HID]
    const float* __restrict__ rw,   // [K, F_IN, HID]
    int N)
{
    __shared__ float xs[64][65];    // padded: conflict-free
    __shared__ float ws[64][64];    // ws[fl][j]: j<32 init, j>=32 root

    int t   = threadIdx.x;
    int n0  = blockIdx.x * 64;
    int nid = t >> 2;
    int jq  = t & 3;
    int n   = n0 + nid;

    float acc[16];
    #pragma unroll
    for (int o = 0; o < 16; o++) acc[o] = 0.f;

    for (int f0 = 0; f0 < F_INC; f0 += 64) {
        #pragma unroll
        for (int i = 0; i < 4; i++) {
            int idx = t + i * 256;
            int nn  = idx >> 4;
            int fq  = idx & 15;
            float4 v = make_float4(0.f, 0.f, 0.f, 0.f);
            if (n0 + nn < N)
                v = *(const float4*)&x[(long long)(n0 + nn) * F_INC + f0 + fq * 4];
            xs[nn][fq * 4 + 0] = v.x;
            xs[nn][fq * 4 + 1] = v.y;
            xs[nn][fq * 4 + 2] = v.z;
            xs[nn][fq * 4 + 3] = v.w;
        }
        #pragma unroll
        for (int i = 0; i < 16; i++) {
            int idx = t + i * 256;
            int fl  = idx >> 6;
            int j   = idx & 63;
            float v;
            if (j < 32)
                v = iw[(j >> 4) * (F_INC * HIDC) + (f0 + fl) * HIDC + (j & 15)];
            else {
                int jj = j - 32;
                v = rw[(jj >> 4) * (F_INC * HIDC) + (f0 + fl) * HIDC + (jj & 15)];
            }
            ws[fl][j] = v;
        }
        __syncthreads();

        #pragma unroll 8
        for (int fl = 0; fl < 64; fl++) {
            float xv = xs[nid][fl];
            const float4* w4 = (const float4*)&ws[fl][jq * 16];
            float4 w0 = w4[0], w1 = w4[1], w2 = w4[2], w3 = w4[3];
            acc[0]  = fmaf(xv, w0.x, acc[0]);
            acc[1]  = fmaf(xv, w0.y, acc[1]);
            acc[2]  = fmaf(xv, w0.z, acc[2]);
            acc[3]  = fmaf(xv, w0.w, acc[3]);
            acc[4]  = fmaf(xv, w1.x, acc[4]);
            acc[5]  = fmaf(xv, w1.y, acc[5]);
            acc[6]  = fmaf(xv, w1.z, acc[6]);
            acc[7]  = fmaf(xv, w1.w, acc[7]);
            acc[8]  = fmaf(xv, w2.x, acc[8]);
            acc[9]  = fmaf(xv, w2.y, acc[9]);
            acc[10] = fmaf(xv, w2.z, acc[10]);
            acc[11] = fmaf(xv, w2.w, acc[11]);
            acc[12] = fmaf(xv, w3.x, acc[12]);
            acc[13] = fmaf(xv, w3.y, acc[13]);
            acc[14] = fmaf(xv, w3.z, acc[14]);
            acc[15] = fmaf(xv, w3.w, acc[15]);
        }
        __syncthreads();
    }

    if (n < N) {
        bool hpath = (jq < 2);
        float scale = hpath ? g_dinv[n] : 1.0f;   // fold dinv[src] into h1 rows
        #pragma unroll
        for (int o = 0; o < 16; o++) acc[o] *= scale;
        float* base = hpath ? &g_h1[n * JW + jq * 16]
                            : &g_r1[n * JW + (jq - 2) * 16];
        float4* d4 = (float4*)base;
        d4[0] = make_float4(acc[0],  acc[1],  acc[2],  acc[3]);
        d4[1] = make_float4(acc[4],  acc[5],  acc[6],  acc[7]);
        d4[2] = make_float4(acc[8],  acc[9],  acc[10], acc[11]);
        d4[3] = make_float4(acc[12], acc[13], acc[14], acc[15]);
    }
}

// ---------------- pull aggregation, width 32: warp per node ----------------
// agg1[n][c] = dinv[n] * sum_{s in N(n)} h1[s][c]   (h1 pre-scaled by dinv[s])
// Inner loop unrolled x4 with independent accumulators -> MLP=4.
__global__ __launch_bounds__(256) void gather32_kernel(int N) {
    int warp = (blockIdx.x * blockDim.x + threadIdx.x) >> 5;
    int lane = threadIdx.x & 31;
    if (warp >= N) return;
    int beg = g_rowptr[warp], end = g_rowptr[warp + 1];
    float a0 = 0.f, a1 = 0.f, a2 = 0.f, a3 = 0.f;
    for (int i = beg; i < end; i += 32) {
        int idx = (i + lane < end) ? g_csr[i + lane] : 0;
        int m = min(32, end - i);
        int j = 0;
        for (; j + 4 <= m; j += 4) {
            int s0 = __shfl_sync(0xffffffffu, idx, j);
            int s1 = __shfl_sync(0xffffffffu, idx, j + 1);
            int s2 = __shfl_sync(0xffffffffu, idx, j + 2);
            int s3 = __shfl_sync(0xffffffffu, idx, j + 3);
            float v0 = g_h1[s0 * JW + lane];
            float v1 = g_h1[s1 * JW + lane];
            float v2 = g_h1[s2 * JW + lane];
            float v3 = g_h1[s3 * JW + lane];
            a0 += v0; a1 += v1; a2 += v2; a3 += v3;
        }
        for (; j < m; j++) {
            int s = __shfl_sync(0xffffffffu, idx, j);
            a0 += g_h1[s * JW + lane];
        }
    }
    g_agg1[warp * JW + lane] = ((a0 + a1) + (a2 + a3)) * g_dinv[warp];
}

// ---------------- pull aggregation, width 16: warp per node, 2 edges/iter --
__global__ __launch_bounds__(256) void gather16_kernel(int N) {
    int warp = (blockIdx.x * blockDim.x + threadIdx.x) >> 5;
    int lane = threadIdx.x & 31;
    if (warp >= N) return;
    int q   = lane & 15;
    int sub = lane >> 4;
    int beg = g_rowptr[warp], end = g_rowptr[warp + 1];
    float a0 = 0.f, a1 = 0.f, a2 = 0.f, a3 = 0.f;
    for (int i = beg; i < end; i += 32) {
        int idx = (i + lane < end) ? g_csr[i + lane] : 0;
        int m = min(32, end - i);
        int j = 0;
        for (; j + 8 <= m; j += 8) {   // 4 pairs per sub-lane -> MLP=4
            int s0 = __shfl_sync(0xffffffffu, idx, j + 0 + sub);
            int s1 = __shfl_sync(0xffffffffu, idx, j + 2 + sub);
            int s2 = __shfl_sync(0xffffffffu, idx, j + 4 + sub);
            int s3 = __shfl_sync(0xffffffffu, idx, j + 6 + sub);
            float v0 = g_hfs[s0 * HIDC + q];
            float v1 = g_hfs[s1 * HIDC + q];
            float v2 = g_hfs[s2 * HIDC + q];
            float v3 = g_hfs[s3 * HIDC + q];
            a0 += v0; a1 += v1; a2 += v2; a3 += v3;
        }
        for (; j < m; j += 2) {
            int jj = j + sub;
            int s = __shfl_sync(0xffffffffu, idx, jj);
            if (jj < m) a0 += g_hfs[s * HIDC + q];
        }
    }
    float acc = (a0 + a1) + (a2 + a3);
    acc += __shfl_xor_sync(0xffffffffu, acc, 16);
    if (sub == 0) g_aggh[warp * HIDC + q] = acc * g_dinv[warp];
}

// ---------------- combine conv1: h = mean_k relu(agg + root + bias) --------
__global__ __launch_bounds__(256) void combine_kernel(
    const float* __restrict__ b1,    // [K, HID] = 32
    float* __restrict__ feat_out,
    int N, int write_feat)
{
    __shared__ float b1s[32];
    int t = threadIdx.x;
    if (t < 32) b1s[t] = b1[t];
    __syncthreads();

    int n = blockIdx.x * blockDim.x + t;
    if (n >= N) return;

    float pre[32];
    const float4* a4 = (const float4*)&g_agg1[n * JW];
    const float4* r4 = (const float4*)&g_r1 [n * JW];
    #pragma unroll
    for (int q = 0; q < 8; q++) {
        float4 av = a4[q], rv = r4[q];
        pre[q * 4 + 0] = av.x + rv.x + b1s[q * 4 + 0];
        pre[q * 4 + 1] = av.y + rv.y + b1s[q * 4 + 1];
        pre[q * 4 + 2] = av.z + rv.z + b1s[q * 4 + 2];
        pre[q * 4 + 3] = av.w + rv.w + b1s[q * 4 + 3];
    }
    float h[16];
    #pragma unroll
    for (int o = 0; o < 16; o++) {
        float a0 = fmaxf(pre[o],      0.f);
        float a1 = fmaxf(pre[16 + o], 0.f);
        h[o] = 0.5f * (a0 + a1);   // mean over K; outer relu is a no-op (>=0)
    }
    float dn = g_dinv[n];
    float4 v0 = make_float4(h[0],  h[1],  h[2],  h[3]);
    float4 v1 = make_float4(h[4],  h[5],  h[6],  h[7]);
    float4 v2 = make_float4(h[8],  h[9],  h[10], h[11]);
    float4 v3 = make_float4(h[12], h[13], h[14], h[15]);
    float4* hf4 = (float4*)&g_hf[n * HIDC];
    hf4[0] = v0; hf4[1] = v1; hf4[2] = v2; hf4[3] = v3;
    float4* hs4 = (float4*)&g_hfs[n * HIDC];
    hs4[0] = make_float4(h[0] * dn,  h[1] * dn,  h[2] * dn,  h[3] * dn);
    hs4[1] = make_float4(h[4] * dn,  h[5] * dn,  h[6] * dn,  h[7] * dn);
    hs4[2] = make_float4(h[8] * dn,  h[9] * dn,  h[10] * dn, h[11] * dn);
    hs4[3] = make_float4(h[12] * dn, h[13] * dn, h[14] * dn, h[15] * dn);
    if (write_feat) {
        float4* f4 = (float4*)&feat_out[(long long)n * CLSC];
        f4[0] = v0; f4[1] = v1; f4[2] = v2; f4[3] = v3;
    }
}

// ---------------- final: logits = (S@h)@Wi + h@Wr + b, then log_softmax ----
__global__ __launch_bounds__(256) void final_kernel(
    const float* __restrict__ iw2,   // [K, HID, C]
    const float* __restrict__ rw2,   // [K, HID, C]
    const float* __restrict__ b2,    // [K, C]
    float* __restrict__ out, int N)
{
    __shared__ float wi[16][16], wr[16][16], bs[16];
    int t = threadIdx.x;
    {
        int o = t >> 4, c = t & 15;
        wi[o][c] = 0.5f * (iw2[o * 16 + c] + iw2[256 + o * 16 + c]);
        wr[o][c] = 0.5f * (rw2[o * 16 + c] + rw2[256 + o * 16 + c]);
    }
    if (t < 16) bs[t] = 0.5f * (b2[t] + b2[16 + t]);
    __syncthreads();

    int n = blockIdx.x * blockDim.x + t;
    if (n >= N) return;

    float ah[16], hh[16];
    const float4* a4 = (const float4*)&g_aggh[n * HIDC];
    const float4* h4 = (const float4*)&g_hf [n * HIDC];
    #pragma unroll
    for (int q = 0; q < 4; q++) {
        float4 av = a4[q], hv = h4[q];
        ah[q * 4 + 0] = av.x; ah[q * 4 + 1] = av.y;
        ah[q * 4 + 2] = av.z; ah[q * 4 + 3] = av.w;
        hh[q * 4 + 0] = hv.x; hh[q * 4 + 1] = hv.y;
        hh[q * 4 + 2] = hv.z; hh[q * 4 + 3] = hv.w;
    }
    float lg[16];
    #pragma unroll
    for (int c = 0; c < 16; c++) lg[c] = bs[c];
    #pragma unroll
    for (int o = 0; o < 16; o++) {
        float a = ah[o], h = hh[o];
        #pragma unroll
        for (int c = 0; c < 16; c++)
            lg[c] = fmaf(a, wi[o][c], fmaf(h, wr[o][c], lg[c]));
    }
    float m = -1e30f;
    #pragma unroll
    for (int c = 0; c < 16; c++) m = fmaxf(m, lg[c]);
    float s = 0.f;
    #pragma unroll
    for (int c = 0; c < 16; c++) s += __expf(lg[c] - m);
    float lse = m + __logf(s);

    float4* o4 = (float4*)&out[(long long)n * CLSC];
    o4[0] = make_float4(lg[0] - lse,  lg[1] - lse,  lg[2] - lse,  lg[3] - lse);
    o4[1] = make_float4(lg[4] - lse,  lg[5] - lse,  lg[6] - lse,  lg[7] - lse);
    o4[2] = make_float4(lg[8] - lse,  lg[9] - lse,  lg[10] - lse, lg[11] - lse);
    o4[3] = make_float4(lg[12] - lse, lg[13] - lse, lg[14] - lse, lg[15] - lse);
}

// ---------------- launch ----------------
extern "C" void kernel_launch(void* const* d_in, const int* in_sizes, int n_in,
                              void* d_out, int out_size) {
    const float* x   = (const float*)d_in[0];
    const void*  ei  = d_in[1];                  // int32 or int64, detected on device
    const float* iw1 = (const float*)d_in[2];
    const float* rw1 = (const float*)d_in[3];
    const float* b1  = (const float*)d_in[4];
    const float* iw2 = (const float*)d_in[5];
    const float* rw2 = (const float*)d_in[6];
    const float* b2  = (const float*)d_in[7];
    float* out = (float*)d_out;

    int N = in_sizes[0] / F_INC;
    int E = in_sizes[1] / 2;
    if (N > NMAX) N = NMAX;
    if (E > EMAX) E = EMAX;

    int write_feat = (out_size >= 2 * N * CLSC) ? 1 : 0;
    float* feat_out = write_feat ? (out + (long long)N * CLSC) : out;

    int nb = (N + 255) / 256;                    // scan blocks (<= 1024)

    detect_kernel<<<1, 256>>>((const unsigned int*)ei);
    zeroi_kernel<<<(N + 1023) / 1024, 1024>>>(N);
    deg_kernel<<<(E + 255) / 256, 256>>>(ei, E);
    scan1_kernel<<<nb, 256>>>(N);
    scan2_kernel<<<1, 512>>>(nb);
    scan3_kernel<<<nb, 256>>>(N);
    fill_kernel<<<(E + 255) / 256, 256>>>(ei, E);
    gemm1_kernel<<<(N + 63) / 64, 256>>>(x, iw1, rw1, N);

    int gblocks = (N * 32 + 255) / 256;          // warp per node
    gather32_kernel<<<gblocks, 256>>>(N);

    combine_kernel<<<nb, 256>>>(b1, feat_out, N, write_feat);

    gather16_kernel<<<gblocks, 256>>>(N);

    final_kernel<<<nb, 256>>>(iw2, rw2, b2, out, N);
}